// round 13
// baseline (speedup 1.0000x reference)
#include <cuda_runtime.h>
#include <math.h>

#define Nn 50000
#define Dd 128
#define Tt 4
#define Ee 150000
#define Hh 8
#define E4  (Tt * Ee)
#define TN  (Tt * Nn)
#define NEG_SLOPE 0.2f
#define EPSF 1e-6f
#define SCAN_NB ((TN + 1023) / 1024)

typedef unsigned long long u64;

// ---------------- scratch (static device globals; no allocation) ----------------
__device__ float g_h[Nn*Dd];
__device__ float g_k[Nn*Dd];
__device__ float g_q[Nn*Dd];
__device__ float g_v[Nn*Dd];
__device__ float g_tmp[Nn*Dd];
__device__ float g_al[TN*Hh];
__device__ float g_ar[TN*Hh];
__device__ float g_xw[(size_t)Tt*Nn*Dd];   // GAT: xw | HGT: qA
__device__ int   g_deg[TN];
__device__ int   g_off[TN];
__device__ int   g_cur[TN];
__device__ int   g_csr[E4];
__device__ int   g_bsum[SCAN_NB];

// ---------------- device helpers ----------------
__device__ __forceinline__ float geluf(float x) {
    return 0.5f * x * (1.0f + erff(x * 0.7071067811865476f));
}
__device__ __forceinline__ const int* pick_ei(int t, const int* e0, const int* e1,
                                              const int* e2, const int* e3) {
    return (t == 0) ? e0 : (t == 1) ? e1 : (t == 2) ? e2 : e3;
}
__device__ __forceinline__ float dot4(float4 a, float4 b) {
    return a.x*b.x + a.y*b.y + a.z*b.z + a.w*b.w;
}
// Blackwell packed fp32 FMA (FFMA2). Bit-exact vs two scalar FFMA .rn.
__device__ __forceinline__ u64 pk2(float x) {
    u64 d; unsigned r = __float_as_uint(x);
    asm("mov.b64 %0, {%1, %1};" : "=l"(d) : "r"(r));
    return d;
}
__device__ __forceinline__ void fma2(u64& c, u64 a, u64 b) {
    asm("fma.rn.f32x2 %0, %1, %2, %3;" : "=l"(c) : "l"(a), "l"(b), "l"(c));
}
__device__ __forceinline__ void upk2(u64 d, float& lo, float& hi) {
    asm("mov.b64 {%0, %1}, %2;" : "=f"(lo), "=f"(hi) : "l"(d));
}

// ---------------- elementwise ----------------
__global__ void add3k(const float4* __restrict__ a, const float4* __restrict__ b,
                      const float4* __restrict__ c, float4* __restrict__ o, int n4) {
    int i = blockIdx.x*blockDim.x + threadIdx.x;
    if (i < n4) {
        float4 x = a[i], y = b[i], z = c[i];
        o[i] = make_float4(x.x+y.x+z.x, x.y+y.y+z.y, x.z+y.z+z.z, x.w+y.w+z.w);
    }
}
__global__ void zeroint(int* __restrict__ p, int n) {
    int i = blockIdx.x*blockDim.x + threadIdx.x;
    if (i < n) p[i] = 0;
}

// ---------------- CSR build (round-9 scan version) ----------------
__global__ void deg_k(const int* __restrict__ e0, const int* __restrict__ e1,
                      const int* __restrict__ e2, const int* __restrict__ e3,
                      int* __restrict__ deg) {
    int idx = blockIdx.x*blockDim.x + threadIdx.x;
    if (idx >= E4) return;
    int t = idx / Ee, e = idx - t*Ee;
    const int* ei = pick_ei(t, e0, e1, e2, e3);
    atomicAdd(&deg[t*Nn + ei[Ee + e]], 1);
}
__global__ void scan_pre(const int* __restrict__ deg, int* __restrict__ bsum) {
    __shared__ int sh[32];
    int g = blockIdx.x*1024 + threadIdx.x;
    int v = (g < TN) ? deg[g] : 0;
    int lane = threadIdx.x & 31, w = threadIdx.x >> 5;
    #pragma unroll
    for (int o = 16; o > 0; o >>= 1) v += __shfl_xor_sync(~0u, v, o);
    if (lane == 0) sh[w] = v;
    __syncthreads();
    if (w == 0) {
        int s = sh[lane];
        #pragma unroll
        for (int o = 16; o > 0; o >>= 1) s += __shfl_xor_sync(~0u, s, o);
        if (lane == 0) bsum[blockIdx.x] = s;
    }
}
__global__ void scan_mid(int* __restrict__ bsum) {
    __shared__ int ws[8];
    int tid = threadIdx.x;
    int v = (tid < SCAN_NB) ? bsum[tid] : 0;
    int lane = tid & 31, w = tid >> 5;
    int x = v;
    #pragma unroll
    for (int o = 1; o < 32; o <<= 1) { int u = __shfl_up_sync(~0u, x, o); if (lane >= o) x += u; }
    if (lane == 31) ws[w] = x;
    __syncthreads();
    if (w == 0 && lane < 8) {
        int y = ws[lane];
        #pragma unroll
        for (int o = 1; o < 8; o <<= 1) { int u = __shfl_up_sync(0xffu, y, o); if (lane >= o) y += u; }
        ws[lane] = y;
    }
    __syncthreads();
    int excl = x - v + (w > 0 ? ws[w-1] : 0);
    if (tid < SCAN_NB) bsum[tid] = excl;
}
__global__ void scan_post(const int* __restrict__ deg, const int* __restrict__ bsum,
                          int* __restrict__ off, int* __restrict__ cur) {
    __shared__ int ws[32];
    int g = blockIdx.x*1024 + threadIdx.x;
    int v = (g < TN) ? deg[g] : 0;
    int lane = threadIdx.x & 31, w = threadIdx.x >> 5;
    int x = v;
    #pragma unroll
    for (int o = 1; o < 32; o <<= 1) { int u = __shfl_up_sync(~0u, x, o); if (lane >= o) x += u; }
    if (lane == 31) ws[w] = x;
    __syncthreads();
    if (w == 0) {
        int y = ws[lane];
        #pragma unroll
        for (int o = 1; o < 32; o <<= 1) { int u = __shfl_up_sync(~0u, y, o); if (lane >= o) y += u; }
        ws[lane] = y;
    }
    __syncthreads();
    int excl = x - v + (w > 0 ? ws[w-1] : 0) + bsum[blockIdx.x];
    if (g < TN) { off[g] = excl; cur[g] = excl; }
}
__global__ void fill_k(const int* __restrict__ e0, const int* __restrict__ e1,
                       const int* __restrict__ e2, const int* __restrict__ e3,
                       int* __restrict__ cur, int* __restrict__ csr) {
    int idx = blockIdx.x*blockDim.x + threadIdx.x;
    if (idx >= E4) return;
    int t = idx / Ee, e = idx - t*Ee;
    const int* ei = pick_ei(t, e0, e1, e2, e3);
    int src = ei[e], dst = ei[Ee + e];
    int slot = atomicAdd(&cur[t*Nn + dst], 1);
    csr[slot] = src;
}

// ---------------- GEMM core macros (128x128 tile, 256 thr, 8x8/thr, f32x2) -----
#define GEMM_STAGE_AND_MAC(Aptr, Wptr, Mval)                                        \
    for (int kc = 0; kc < 8; kc++) {                                                \
        __syncthreads();                                                            \
        _Pragma("unroll")                                                           \
        for (int j = 0; j < 2; j++) {                                               \
            int idx = tid + j*256;                                                  \
            int r = idx & 127, kq = idx >> 7;                                       \
            int gr = br + r;                                                        \
            float4 av = (gr < (Mval)) ? *(const float4*)((Aptr) + (size_t)gr*Dd + kc*16 + kq*4) \
                                      : make_float4(0,0,0,0);                       \
            As[kq*4+0][r] = av.x;                                                   \
            As[kq*4+1][r] = av.y;                                                   \
            As[kq*4+2][r] = av.z;                                                   \
            As[kq*4+3][r] = av.w;                                                   \
        }                                                                           \
        _Pragma("unroll")                                                           \
        for (int j = 0; j < 2; j++) {                                               \
            int idx = tid + j*256;                                                  \
            int k = idx >> 5, nq = idx & 31;                                        \
            *(float4*)(&Ws[k][nq*4]) = *(const float4*)((Wptr) + (size_t)(kc*16 + k)*Dd + nq*4); \
        }                                                                           \
        __syncthreads();                                                            \
        _Pragma("unroll")                                                           \
        for (int k = 0; k < 16; k++) {                                              \
            float4 a0 = *(const float4*)(&As[k][ty*8]);                             \
            float4 a1 = *(const float4*)(&As[k][ty*8+4]);                           \
            const u64* w0 = (const u64*)(&Ws[k][tx*4]);                             \
            const u64* w1 = (const u64*)(&Ws[k][64 + tx*4]);                        \
            u64 bq0 = w0[0], bq1 = w0[1], bq2 = w1[0], bq3 = w1[1];                 \
            float av[8] = {a0.x,a0.y,a0.z,a0.w,a1.x,a1.y,a1.z,a1.w};                \
            _Pragma("unroll")                                                       \
            for (int i = 0; i < 8; i++) {                                           \
                u64 ad = pk2(av[i]);                                                \
                fma2(acc2[i][0], ad, bq0);                                          \
                fma2(acc2[i][1], ad, bq1);                                          \
                fma2(acc2[i][2], ad, bq2);                                          \
                fma2(acc2[i][3], ad, bq3);                                          \
            }                                                                       \
        }                                                                           \
    }

#define GEMM_UNPACK()                                                               \
    float acc[8][8];                                                                \
    _Pragma("unroll")                                                               \
    for (int i = 0; i < 8; i++) {                                                   \
        _Pragma("unroll")                                                           \
        for (int j2 = 0; j2 < 4; j2++)                                              \
            upk2(acc2[i][j2], acc[i][j2*2], acc[i][j2*2+1]);                        \
    }

// ---------------- GEMM: C[Mx128] = A[Mx128] @ W[128x128] (+ bias) ----------------
template <bool ALAR>
__global__ void __launch_bounds__(256)
gemm_ff(const float* __restrict__ A, const float* __restrict__ Wbase,
        const float* __restrict__ bias, float* __restrict__ Cbase,
        const float* __restrict__ asb, const float* __restrict__ adb,
        float* __restrict__ al, float* __restrict__ ar, int M) {
    __shared__ float As[16][128];
    __shared__ float Ws[16][128];
    const int t = blockIdx.y;
    const float* W = Wbase + (size_t)t*Dd*Dd;
    float* C = Cbase + (size_t)t*M*Dd;
    const int br = blockIdx.x * 128;
    const int tid = threadIdx.x;
    const int tx = tid & 15, ty = tid >> 4;

    u64 acc2[8][4];
    #pragma unroll
    for (int i = 0; i < 8; i++)
        #pragma unroll
        for (int j = 0; j < 4; j++) acc2[i][j] = 0ull;

    GEMM_STAGE_AND_MAC(A, W, M)
    GEMM_UNPACK()

    float4 bb0 = make_float4(0,0,0,0), bb1 = make_float4(0,0,0,0);
    if (bias) {
        bb0 = *(const float4*)(bias + tx*4);
        bb1 = *(const float4*)(bias + 64 + tx*4);
    }
    float4 s0, s1, d0, d1;
    if (ALAR) {
        s0 = *(const float4*)(asb + t*Dd + tx*4);
        s1 = *(const float4*)(asb + t*Dd + 64 + tx*4);
        d0 = *(const float4*)(adb + t*Dd + tx*4);
        d1 = *(const float4*)(adb + t*Dd + 64 + tx*4);
    }
    #pragma unroll
    for (int i = 0; i < 8; i++) {
        int gr = br + ty*8 + i;
        float4 o0 = make_float4(acc[i][0]+bb0.x, acc[i][1]+bb0.y,
                                acc[i][2]+bb0.z, acc[i][3]+bb0.w);
        float4 o1 = make_float4(acc[i][4]+bb1.x, acc[i][5]+bb1.y,
                                acc[i][6]+bb1.z, acc[i][7]+bb1.w);
        if (gr < M) {
            *(float4*)(C + (size_t)gr*Dd + tx*4) = o0;
            *(float4*)(C + (size_t)gr*Dd + 64 + tx*4) = o1;
        }
        if (ALAR) {
            float pa0 = acc[i][0]*s0.x + acc[i][1]*s0.y + acc[i][2]*s0.z + acc[i][3]*s0.w;
            float pa1 = acc[i][4]*s1.x + acc[i][5]*s1.y + acc[i][6]*s1.z + acc[i][7]*s1.w;
            float pr0 = acc[i][0]*d0.x + acc[i][1]*d0.y + acc[i][2]*d0.z + acc[i][3]*d0.w;
            float pr1 = acc[i][4]*d1.x + acc[i][5]*d1.y + acc[i][6]*d1.z + acc[i][7]*d1.w;
            pa0 += __shfl_xor_sync(~0u, pa0, 1); pa0 += __shfl_xor_sync(~0u, pa0, 2);
            pa1 += __shfl_xor_sync(~0u, pa1, 1); pa1 += __shfl_xor_sync(~0u, pa1, 2);
            pr0 += __shfl_xor_sync(~0u, pr0, 1); pr0 += __shfl_xor_sync(~0u, pr0, 2);
            pr1 += __shfl_xor_sync(~0u, pr1, 1); pr1 += __shfl_xor_sync(~0u, pr1, 2);
            if (gr < M && (tx & 3) == 0) {
                int base = ((t*Nn) + gr)*Hh;
                int hh0 = tx >> 2, hh1 = 4 + (tx >> 2);
                al[base + hh0] = pa0;
                al[base + hh1] = pa1;
                ar[base + hh0] = pr0;
                ar[base + hh1] = pr1;
            }
        }
    }
}

// ---------------- fused k/q/v GEMM ----------------
__global__ void __launch_bounds__(256)
gemm_kqv(const float* __restrict__ A,
         const float* __restrict__ Wk, const float* __restrict__ bk, float* __restrict__ Ck,
         const float* __restrict__ Wq, const float* __restrict__ bq, float* __restrict__ Cq,
         const float* __restrict__ Wv, const float* __restrict__ bv, float* __restrict__ Cv) {
    __shared__ float As[16][128];
    __shared__ float Ws[16][128];
    const int t = blockIdx.y;
    const float* W = (t == 0) ? Wk : (t == 1) ? Wq : Wv;
    const float* bias = (t == 0) ? bk : (t == 1) ? bq : bv;
    float* C = (t == 0) ? Ck : (t == 1) ? Cq : Cv;
    const int br = blockIdx.x * 128;
    const int tid = threadIdx.x;
    const int tx = tid & 15, ty = tid >> 4;

    u64 acc2[8][4];
    #pragma unroll
    for (int i = 0; i < 8; i++)
        #pragma unroll
        for (int j = 0; j < 4; j++) acc2[i][j] = 0ull;

    GEMM_STAGE_AND_MAC(A, W, Nn)
    GEMM_UNPACK()

    float4 bb0 = *(const float4*)(bias + tx*4);
    float4 bb1 = *(const float4*)(bias + 64 + tx*4);
    #pragma unroll
    for (int i = 0; i < 8; i++) {
        int gr = br + ty*8 + i;
        if (gr < Nn) {
            *(float4*)(C + (size_t)gr*Dd + tx*4) =
                make_float4(acc[i][0]+bb0.x, acc[i][1]+bb0.y, acc[i][2]+bb0.z, acc[i][3]+bb0.w);
            *(float4*)(C + (size_t)gr*Dd + 64 + tx*4) =
                make_float4(acc[i][4]+bb1.x, acc[i][5]+bb1.y, acc[i][6]+bb1.z, acc[i][7]+bb1.w);
        }
    }
}

// ---------------- Final GEMM + HGT post fused ----------------------------------
__global__ void __launch_bounds__(256)
gemm_wo_post(const float* __restrict__ A, const float* __restrict__ W,
             const float* __restrict__ bias, const float* __restrict__ h,
             const float* __restrict__ g, const float* __restrict__ skip,
             float* __restrict__ out) {
    __shared__ float As[16][128];
    __shared__ float Ws[16][128];
    const int br = blockIdx.x * 128;
    const int tid = threadIdx.x;
    const int tx = tid & 15, ty = tid >> 4;

    u64 acc2[8][4];
    #pragma unroll
    for (int i = 0; i < 8; i++)
        #pragma unroll
        for (int j = 0; j < 4; j++) acc2[i][j] = 0ull;

    GEMM_STAGE_AND_MAC(A, W, Nn)
    GEMM_UNPACK()

    float beta = 1.f / (1.f + expf(-skip[0]));
    float omb = 1.f - beta;
    float4 bb0 = *(const float4*)(bias + tx*4);
    float4 bb1 = *(const float4*)(bias + 64 + tx*4);
    float4 g0 = *(const float4*)(g + tx*4);
    float4 g1 = *(const float4*)(g + 64 + tx*4);

    #pragma unroll
    for (int i = 0; i < 8; i++) {
        int gr = br + ty*8 + i;
        if (gr >= Nn) continue;
        float4 h0 = *(const float4*)(h + (size_t)gr*Dd + tx*4);
        float4 h1 = *(const float4*)(h + (size_t)gr*Dd + 64 + tx*4);
        float u[8];
        u[0] = beta*(acc[i][0]+bb0.x) + omb*h0.x;
        u[1] = beta*(acc[i][1]+bb0.y) + omb*h0.y;
        u[2] = beta*(acc[i][2]+bb0.z) + omb*h0.z;
        u[3] = beta*(acc[i][3]+bb0.w) + omb*h0.w;
        u[4] = beta*(acc[i][4]+bb1.x) + omb*h1.x;
        u[5] = beta*(acc[i][5]+bb1.y) + omb*h1.y;
        u[6] = beta*(acc[i][6]+bb1.z) + omb*h1.z;
        u[7] = beta*(acc[i][7]+bb1.w) + omb*h1.w;
        float ss = 0.f;
        #pragma unroll
        for (int j = 0; j < 8; j++) ss += u[j]*u[j];
        ss += __shfl_xor_sync(~0u, ss, 1);
        ss += __shfl_xor_sync(~0u, ss, 2);
        ss += __shfl_xor_sync(~0u, ss, 4);
        ss += __shfl_xor_sync(~0u, ss, 8);
        float inv = rsqrtf(ss * (1.0f/Dd) + EPSF);
        float4 r0, r1;
        r0.x = geluf(h0.x + g0.x*u[0]*inv);
        r0.y = geluf(h0.y + g0.y*u[1]*inv);
        r0.z = geluf(h0.z + g0.z*u[2]*inv);
        r0.w = geluf(h0.w + g0.w*u[3]*inv);
        r1.x = geluf(h1.x + g1.x*u[4]*inv);
        r1.y = geluf(h1.y + g1.y*u[5]*inv);
        r1.z = geluf(h1.z + g1.z*u[6]*inv);
        r1.w = geluf(h1.w + g1.w*u[7]*inv);
        *(float4*)(out + (size_t)gr*Dd + tx*4) = r0;
        *(float4*)(out + (size_t)gr*Dd + 64 + tx*4) = r1;
    }
}

// ---------------- GAT gather: one BLOCK per dst node, one warp per type --------
__global__ void gat_gather_b(const int* __restrict__ csr, const int* __restrict__ off,
                             const int* __restrict__ deg, const float* __restrict__ al,
                             const float* __restrict__ ar, const float* __restrict__ xw,
                             const float* __restrict__ b, const float* __restrict__ g,
                             float* __restrict__ h) {
    int n = blockIdx.x;
    int tid = threadIdx.x;
    int t = tid >> 5, lane = tid & 31;
    int hh = lane >> 2;
    __shared__ float smf[4][128];
    __shared__ float sw[4];

    {
        int i = t*Nn + n;
        float arn = ar[(size_t)i*Hh + hh];
        float v = al[(size_t)i*Hh + hh] + arn;    // self loop
        v = v > 0.f ? v : NEG_SLOPE*v;
        float p = expf(v);
        float s = p;
        float4 x = *(const float4*)(xw + (size_t)i*Dd + lane*4);
        float4 f = make_float4(x.x*p, x.y*p, x.z*p, x.w*p);

        const float* alt = al + (size_t)t*Nn*Hh;
        const float* xwt = xw + (size_t)t*Nn*Dd;
        int st = off[i], dg = deg[i];
        for (int j0 = 0; j0 < dg; j0 += 32) {
            int myS = (j0 + lane < dg) ? csr[st + j0 + lane] : 0;
            int cnt = min(32, dg - j0);
            for (int j = 0; j < cnt; j += 4) {
                int s0 = __shfl_sync(~0u, myS, j);
                int s1 = __shfl_sync(~0u, myS, (j+1) & 31);
                int s2 = __shfl_sync(~0u, myS, (j+2) & 31);
                int s3 = __shfl_sync(~0u, myS, (j+3) & 31);
                float a0 = alt[(size_t)s0*Hh + hh];
                float a1 = alt[(size_t)s1*Hh + hh];
                float a2 = alt[(size_t)s2*Hh + hh];
                float a3 = alt[(size_t)s3*Hh + hh];
                float4 x0 = *(const float4*)(xwt + (size_t)s0*Dd + lane*4);
                float4 x1 = *(const float4*)(xwt + (size_t)s1*Dd + lane*4);
                float4 x2 = *(const float4*)(xwt + (size_t)s2*Dd + lane*4);
                float4 x3 = *(const float4*)(xwt + (size_t)s3*Dd + lane*4);
                float v0 = a0 + arn; v0 = v0 > 0.f ? v0 : NEG_SLOPE*v0;
                float v1 = a1 + arn; v1 = v1 > 0.f ? v1 : NEG_SLOPE*v1;
                float v2 = a2 + arn; v2 = v2 > 0.f ? v2 : NEG_SLOPE*v2;
                float v3 = a3 + arn; v3 = v3 > 0.f ? v3 : NEG_SLOPE*v3;
                float p0 = expf(v0);
                float p1 = (j+1 < cnt) ? expf(v1) : 0.f;
                float p2 = (j+2 < cnt) ? expf(v2) : 0.f;
                float p3 = (j+3 < cnt) ? expf(v3) : 0.f;
                s += p0 + p1 + p2 + p3;
                f.x += x0.x*p0 + x1.x*p1 + x2.x*p2 + x3.x*p3;
                f.y += x0.y*p0 + x1.y*p1 + x2.y*p2 + x3.y*p3;
                f.z += x0.z*p0 + x1.z*p1 + x2.z*p2 + x3.z*p3;
                f.w += x0.w*p0 + x1.w*p1 + x2.w*p2 + x3.w*p3;
            }
        }
        float inv = 1.f / s;
        *(float4*)(&smf[t][lane*4]) = make_float4(f.x*inv, f.y*inv, f.z*inv, f.w*inv);
    }
    __syncthreads();

    int d = tid;
    float a = smf[0][d] + smf[1][d] + smf[2][d] + smf[3][d]
            + b[d] + b[Dd + d] + b[2*Dd + d] + b[3*Dd + d];
    float ss = a*a;
    #pragma unroll
    for (int o = 16; o > 0; o >>= 1) ss += __shfl_xor_sync(0xffffffffu, ss, o);
    if (lane == 0) sw[t] = ss;
    __syncthreads();
    float tot = sw[0] + sw[1] + sw[2] + sw[3];
    float inv2 = rsqrtf(tot * (1.0f/Dd) + EPSF);
    int i = n*Dd + d;
    h[i] = geluf(h[i] + g[d] * a * inv2);
}

// ---------------- HGT: dense qA precompute: qA[t][n][h*16+i] = arel[t,h] @ q[n,h] -
__global__ void hgt_qA(const float* __restrict__ q, const float* __restrict__ arel,
                       float* __restrict__ qA) {
    int idx = blockIdx.x*blockDim.x + threadIdx.x;
    if (idx >= Nn*Tt*Hh) return;
    int h = idx & 7, t = (idx >> 3) & 3, n = idx >> 5;
    const float* xp = q + (size_t)n*Dd + h*16;
    const float* Rp = arel + (t*Hh + h)*256;
    float xr[16];
    #pragma unroll
    for (int i = 0; i < 4; i++) ((float4*)xr)[i] = ((const float4*)xp)[i];
    float o[16];
    #pragma unroll
    for (int i = 0; i < 16; i++) o[i] = 0.f;
    #pragma unroll
    for (int j = 0; j < 16; j++) {
        float xj = xr[j];
        #pragma unroll
        for (int i = 0; i < 16; i++)
            o[i] += xj * Rp[i*16 + j];
    }
    float* op = qA + ((size_t)t*Nn + n)*Dd + h*16;
    #pragma unroll
    for (int i = 0; i < 4; i++) ((float4*)op)[i] = ((float4*)o)[i];
}

// ---------------- HGT gather: qA read coalesced; mrel applied via smem ---------
__global__ void hgt_gather_b(const int* __restrict__ csr, const int* __restrict__ off,
                             const int* __restrict__ deg, const float* __restrict__ k,
                             const float* __restrict__ qA, const float* __restrict__ v,
                             const float* __restrict__ mrel, const float* __restrict__ prel,
                             float* __restrict__ out) {
    int n = blockIdx.x;
    int tid = threadIdx.x;
    int t = tid >> 5, lane = tid & 31;
    int hh = lane >> 2;
    __shared__ float smacc[4][128];
    __shared__ float sms[4][8];

    {
        float4 qa = *(const float4*)(qA + ((size_t)t*Nn + n)*Dd + lane*4);
        float pr = prel[t*Hh + hh] * 0.25f;   // / sqrt(16)

        float4 aggv = make_float4(0,0,0,0);
        float s = 0.f;
        int i0 = t*Nn + n, st = off[i0], dg = deg[i0];
        for (int j0 = 0; j0 < dg; j0 += 32) {
            int myS = (j0 + lane < dg) ? csr[st + j0 + lane] : 0;
            int cnt = min(32, dg - j0);
            for (int j = 0; j < cnt; j += 4) {
                int s0 = __shfl_sync(~0u, myS, j);
                int s1 = __shfl_sync(~0u, myS, (j+1) & 31);
                int s2 = __shfl_sync(~0u, myS, (j+2) & 31);
                int s3 = __shfl_sync(~0u, myS, (j+3) & 31);
                float4 k0 = *(const float4*)(k + (size_t)s0*Dd + lane*4);
                float4 k1 = *(const float4*)(k + (size_t)s1*Dd + lane*4);
                float4 k2 = *(const float4*)(k + (size_t)s2*Dd + lane*4);
                float4 k3 = *(const float4*)(k + (size_t)s3*Dd + lane*4);
                float4 v0 = *(const float4*)(v + (size_t)s0*Dd + lane*4);
                float4 v1 = *(const float4*)(v + (size_t)s1*Dd + lane*4);
                float4 v2 = *(const float4*)(v + (size_t)s2*Dd + lane*4);
                float4 v3 = *(const float4*)(v + (size_t)s3*Dd + lane*4);
                float pt0 = dot4(k0, qa);
                float pt1 = dot4(k1, qa);
                float pt2 = dot4(k2, qa);
                float pt3 = dot4(k3, qa);
                pt0 += __shfl_xor_sync(~0u, pt0, 1); pt0 += __shfl_xor_sync(~0u, pt0, 2);
                pt1 += __shfl_xor_sync(~0u, pt1, 1); pt1 += __shfl_xor_sync(~0u, pt1, 2);
                pt2 += __shfl_xor_sync(~0u, pt2, 1); pt2 += __shfl_xor_sync(~0u, pt2, 2);
                pt3 += __shfl_xor_sync(~0u, pt3, 1); pt3 += __shfl_xor_sync(~0u, pt3, 2);
                float p0 = expf(pt0 * pr);
                float p1 = (j+1 < cnt) ? expf(pt1 * pr) : 0.f;
                float p2 = (j+2 < cnt) ? expf(pt2 * pr) : 0.f;
                float p3 = (j+3 < cnt) ? expf(pt3 * pr) : 0.f;
                s += p0 + p1 + p2 + p3;
                aggv.x += v0.x*p0 + v1.x*p1 + v2.x*p2 + v3.x*p3;
                aggv.y += v0.y*p0 + v1.y*p1 + v2.y*p2 + v3.y*p3;
                aggv.z += v0.z*p0 + v1.z*p1 + v2.z*p2 + v3.z*p3;
                aggv.w += v0.w*p0 + v1.w*p1 + v2.w*p2 + v3.w*p3;
            }
        }
        *(float4*)(&smacc[t][lane*4]) = aggv;
        // s identical across the 4 lanes of a head quad; lane with qd==0 writes.
        if ((lane & 3) == 0) sms[t][hh] = s;
    }
    __syncthreads();

    // thread d: out[d] = gelu( (sum_t aggv_t @ mrel[t][hh]) [d] / stot )
    int d = tid;
    int dh = d >> 4, dq = d & 15;
    float a = 0.f;
    #pragma unroll
    for (int t2 = 0; t2 < Tt; t2++) {
        const float* M = mrel + (size_t)((t2*Hh + dh)*16)*16;
        const float* av = &smacc[t2][dh*16];
        float sum = 0.f;
        #pragma unroll
        for (int j = 0; j < 16; j++)
            sum += av[j] * M[j*16 + dq];
        a += sum;
    }
    float stot = sms[0][dh] + sms[1][dh] + sms[2][dh] + sms[3][dh];
    float inv = 1.f / (stot > 0.f ? stot : 1.f);
    out[(size_t)n*Dd + d] = geluf(a * inv);
}

// ---------------- host launch ----------------
extern "C" void kernel_launch(void* const* d_in, const int* in_sizes, int n_in,
                              void* d_out, int out_size) {
    const float* zL  = (const float*)d_in[0];
    const float* zH  = (const float*)d_in[1];
    const float* xe  = (const float*)d_in[2];
    const float* W1  = (const float*)d_in[3];
    const float* as1 = (const float*)d_in[4];
    const float* ad1 = (const float*)d_in[5];
    const float* b1  = (const float*)d_in[6];
    const float* W2  = (const float*)d_in[7];
    const float* as2 = (const float*)d_in[8];
    const float* ad2 = (const float*)d_in[9];
    const float* b2  = (const float*)d_in[10];
    const float* Wk  = (const float*)d_in[11];
    const float* bk  = (const float*)d_in[12];
    const float* Wq  = (const float*)d_in[13];
    const float* bq  = (const float*)d_in[14];
    const float* Wv  = (const float*)d_in[15];
    const float* bv  = (const float*)d_in[16];
    const float* arel= (const float*)d_in[17];
    const float* mrel= (const float*)d_in[18];
    const float* prel= (const float*)d_in[19];
    const float* Wo  = (const float*)d_in[20];
    const float* bo  = (const float*)d_in[21];
    const float* skip= (const float*)d_in[22];
    const float* g1  = (const float*)d_in[23];
    const float* g2  = (const float*)d_in[24];
    const float* g3  = (const float*)d_in[25];
    const int* ei[4] = {(const int*)d_in[26], (const int*)d_in[27],
                        (const int*)d_in[28], (const int*)d_in[29]};

    float *h_, *k_, *q_, *v_, *tmp_, *al_, *ar_, *xw_;
    int *deg_, *off_, *cur_, *csr_, *bsum_;
    cudaGetSymbolAddress((void**)&h_,   g_h);
    cudaGetSymbolAddress((void**)&k_,   g_k);
    cudaGetSymbolAddress((void**)&q_,   g_q);
    cudaGetSymbolAddress((void**)&v_,   g_v);
    cudaGetSymbolAddress((void**)&tmp_, g_tmp);
    cudaGetSymbolAddress((void**)&al_,  g_al);
    cudaGetSymbolAddress((void**)&ar_,  g_ar);
    cudaGetSymbolAddress((void**)&xw_,  g_xw);
    cudaGetSymbolAddress((void**)&deg_, g_deg);
    cudaGetSymbolAddress((void**)&off_, g_off);
    cudaGetSymbolAddress((void**)&cur_, g_cur);
    cudaGetSymbolAddress((void**)&csr_, g_csr);
    cudaGetSymbolAddress((void**)&bsum_,g_bsum);

    const int nd = Nn*Dd;
    const int TPB = 256;
    const int gemm_grid = (Nn + 127) / 128;

    // Launch order: hgt_gather reachable only late; gemm_ff<true> stays launch #4.
    zeroint<<<(TN + TPB-1)/TPB, TPB>>>(deg_, TN);                                   // 1
    deg_k<<<(E4 + TPB-1)/TPB, TPB>>>(ei[0], ei[1], ei[2], ei[3], deg_);             // 2
    add3k<<<(nd/4 + TPB-1)/TPB, TPB>>>((const float4*)zL, (const float4*)zH,
                                       (const float4*)xe, (float4*)h_, nd/4);       // 3
    gemm_ff<true><<<dim3(gemm_grid, Tt), TPB>>>(h_, W1, nullptr, xw_,
                                                as1, ad1, al_, ar_, Nn);            // 4 (profiled)
    scan_pre<<<SCAN_NB, 1024>>>(deg_, bsum_);                                       // 5
    scan_mid<<<1, 256>>>(bsum_);                                                    // 6
    scan_post<<<SCAN_NB, 1024>>>(deg_, bsum_, off_, cur_);                          // 7
    fill_k<<<(E4 + TPB-1)/TPB, TPB>>>(ei[0], ei[1], ei[2], ei[3], cur_, csr_);      // 8

    gat_gather_b<<<Nn, 128>>>(csr_, off_, deg_, al_, ar_, xw_, b1, g1, h_);         // 9

    gemm_ff<true><<<dim3(gemm_grid, Tt), TPB>>>(h_, W2, nullptr, xw_,
                                                as2, ad2, al_, ar_, Nn);            // 10
    gat_gather_b<<<Nn, 128>>>(csr_, off_, deg_, al_, ar_, xw_, b2, g2, h_);         // 11

    // HGT
    gemm_kqv<<<dim3(gemm_grid, 3), TPB>>>(h_, Wk, bk, k_, Wq, bq, q_, Wv, bv, v_);  // 12
    hgt_qA<<<(Nn*Tt*Hh + TPB-1)/TPB, TPB>>>(q_, arel, xw_);                         // 13
    hgt_gather_b<<<Nn, 128>>>(csr_, off_, deg_, k_, xw_, v_, mrel, prel, tmp_);     // 14
    gemm_wo_post<<<gemm_grid, TPB>>>(tmp_, Wo, bo, h_, g3, skip, (float*)d_out);    // 15
}

// round 14
// speedup vs baseline: 1.8673x; 1.8673x over previous
#include <cuda_runtime.h>
#include <math.h>

#define Nn 50000
#define Dd 128
#define Tt 4
#define Ee 150000
#define Hh 8
#define E4  (Tt * Ee)
#define TN  (Tt * Nn)
#define NEG_SLOPE 0.2f
#define EPSF 1e-6f
#define SCAN_NB ((TN + 1023) / 1024)

typedef unsigned long long u64;

// ---------------- scratch (static device globals; no allocation) ----------------
__device__ float g_h[Nn*Dd];
__device__ float g_k[Nn*Dd];
__device__ float g_q[Nn*Dd];
__device__ float g_v[Nn*Dd];
__device__ float g_tmp[Nn*Dd];
__device__ float g_al[TN*Hh];
__device__ float g_ar[TN*Hh];
__device__ float g_xw[(size_t)Tt*Nn*Dd];
__device__ int   g_deg[TN];
__device__ int   g_off[TN];
__device__ int   g_cur[TN];
__device__ int   g_csr[E4];
__device__ int   g_bsum[SCAN_NB];

// ---------------- device helpers ----------------
__device__ __forceinline__ float geluf(float x) {
    return 0.5f * x * (1.0f + erff(x * 0.7071067811865476f));
}
__device__ __forceinline__ const int* pick_ei(int t, const int* e0, const int* e1,
                                              const int* e2, const int* e3) {
    return (t == 0) ? e0 : (t == 1) ? e1 : (t == 2) ? e2 : e3;
}
__device__ __forceinline__ float dot4(float4 a, float4 b) {
    return a.x*b.x + a.y*b.y + a.z*b.z + a.w*b.w;
}
__device__ __forceinline__ float4 shfl4(float4 v, int src) {
    float4 r;
    r.x = __shfl_sync(0xffffffffu, v.x, src);
    r.y = __shfl_sync(0xffffffffu, v.y, src);
    r.z = __shfl_sync(0xffffffffu, v.z, src);
    r.w = __shfl_sync(0xffffffffu, v.w, src);
    return r;
}
// Blackwell packed fp32 FMA (FFMA2). Bit-exact vs two scalar FFMA .rn.
__device__ __forceinline__ u64 pk2(float x) {
    u64 d; unsigned r = __float_as_uint(x);
    asm("mov.b64 %0, {%1, %1};" : "=l"(d) : "r"(r));
    return d;
}
__device__ __forceinline__ void fma2(u64& c, u64 a, u64 b) {
    asm("fma.rn.f32x2 %0, %1, %2, %3;" : "=l"(c) : "l"(a), "l"(b), "l"(c));
}
__device__ __forceinline__ void upk2(u64 d, float& lo, float& hi) {
    asm("mov.b64 {%0, %1}, %2;" : "=f"(lo), "=f"(hi) : "l"(d));
}

// ---------------- elementwise ----------------
__global__ void add3k(const float4* __restrict__ a, const float4* __restrict__ b,
                      const float4* __restrict__ c, float4* __restrict__ o, int n4) {
    int i = blockIdx.x*blockDim.x + threadIdx.x;
    if (i < n4) {
        float4 x = a[i], y = b[i], z = c[i];
        o[i] = make_float4(x.x+y.x+z.x, x.y+y.y+z.y, x.z+y.z+z.z, x.w+y.w+z.w);
    }
}
__global__ void zeroint(int* __restrict__ p, int n) {
    int i = blockIdx.x*blockDim.x + threadIdx.x;
    if (i < n) p[i] = 0;
}

// ---------------- CSR build ----------------
__global__ void deg_k(const int* __restrict__ e0, const int* __restrict__ e1,
                      const int* __restrict__ e2, const int* __restrict__ e3,
                      int* __restrict__ deg) {
    int idx = blockIdx.x*blockDim.x + threadIdx.x;
    if (idx >= E4) return;
    int t = idx / Ee, e = idx - t*Ee;
    const int* ei = pick_ei(t, e0, e1, e2, e3);
    atomicAdd(&deg[t*Nn + ei[Ee + e]], 1);
}
__global__ void scan_pre(const int* __restrict__ deg, int* __restrict__ bsum) {
    __shared__ int sh[32];
    int g = blockIdx.x*1024 + threadIdx.x;
    int v = (g < TN) ? deg[g] : 0;
    int lane = threadIdx.x & 31, w = threadIdx.x >> 5;
    #pragma unroll
    for (int o = 16; o > 0; o >>= 1) v += __shfl_xor_sync(~0u, v, o);
    if (lane == 0) sh[w] = v;
    __syncthreads();
    if (w == 0) {
        int s = sh[lane];
        #pragma unroll
        for (int o = 16; o > 0; o >>= 1) s += __shfl_xor_sync(~0u, s, o);
        if (lane == 0) bsum[blockIdx.x] = s;
    }
}
__global__ void scan_mid(int* __restrict__ bsum) {
    __shared__ int ws[8];
    int tid = threadIdx.x;
    int v = (tid < SCAN_NB) ? bsum[tid] : 0;
    int lane = tid & 31, w = tid >> 5;
    int x = v;
    #pragma unroll
    for (int o = 1; o < 32; o <<= 1) { int u = __shfl_up_sync(~0u, x, o); if (lane >= o) x += u; }
    if (lane == 31) ws[w] = x;
    __syncthreads();
    if (w == 0 && lane < 8) {
        int y = ws[lane];
        #pragma unroll
        for (int o = 1; o < 8; o <<= 1) { int u = __shfl_up_sync(0xffu, y, o); if (lane >= o) y += u; }
        ws[lane] = y;
    }
    __syncthreads();
    int excl = x - v + (w > 0 ? ws[w-1] : 0);
    if (tid < SCAN_NB) bsum[tid] = excl;
}
__global__ void scan_post(const int* __restrict__ deg, const int* __restrict__ bsum,
                          int* __restrict__ off, int* __restrict__ cur) {
    __shared__ int ws[32];
    int g = blockIdx.x*1024 + threadIdx.x;
    int v = (g < TN) ? deg[g] : 0;
    int lane = threadIdx.x & 31, w = threadIdx.x >> 5;
    int x = v;
    #pragma unroll
    for (int o = 1; o < 32; o <<= 1) { int u = __shfl_up_sync(~0u, x, o); if (lane >= o) x += u; }
    if (lane == 31) ws[w] = x;
    __syncthreads();
    if (w == 0) {
        int y = ws[lane];
        #pragma unroll
        for (int o = 1; o < 32; o <<= 1) { int u = __shfl_up_sync(~0u, y, o); if (lane >= o) y += u; }
        ws[lane] = y;
    }
    __syncthreads();
    int excl = x - v + (w > 0 ? ws[w-1] : 0) + bsum[blockIdx.x];
    if (g < TN) { off[g] = excl; cur[g] = excl; }
}
__global__ void fill_k(const int* __restrict__ e0, const int* __restrict__ e1,
                       const int* __restrict__ e2, const int* __restrict__ e3,
                       int* __restrict__ cur, int* __restrict__ csr) {
    int idx = blockIdx.x*blockDim.x + threadIdx.x;
    if (idx >= E4) return;
    int t = idx / Ee, e = idx - t*Ee;
    const int* ei = pick_ei(t, e0, e1, e2, e3);
    int src = ei[e], dst = ei[Ee + e];
    int slot = atomicAdd(&cur[t*Nn + dst], 1);
    csr[slot] = src;
}

// ---------------- GEMM core macro: software-pipelined staging -------------------
// Prefetch chunk kc+1 into registers right after the post-store barrier, so the
// global-load latency overlaps the FFMA2 burst of chunk kc.
#define GEMM_STAGE_AND_MAC(Aptr, Wptr, Mval)                                        \
    float4 pA0, pA1, pW0, pW1;                                                      \
    {                                                                               \
        int r0 = tid & 127, kq0 = tid >> 7;                                         \
        int r1 = r0, kq1 = kq0 + 2;                                                 \
        int gr0 = br + r0;                                                          \
        pA0 = (gr0 < (Mval)) ? *(const float4*)((Aptr) + (size_t)gr0*Dd + kq0*4)    \
                             : make_float4(0,0,0,0);                                \
        pA1 = (gr0 < (Mval)) ? *(const float4*)((Aptr) + (size_t)gr0*Dd + kq1*4)    \
                             : make_float4(0,0,0,0);                                \
        (void)r1;                                                                   \
        int k0 = tid >> 5, nq0 = tid & 31;                                          \
        pW0 = *(const float4*)((Wptr) + (size_t)k0*Dd + nq0*4);                     \
        pW1 = *(const float4*)((Wptr) + (size_t)(k0 + 8)*Dd + nq0*4);               \
    }                                                                               \
    for (int kc = 0; kc < 8; kc++) {                                                \
        __syncthreads();                                                            \
        {                                                                           \
            int r = tid & 127, kq = tid >> 7;                                       \
            As[kq*4+0][r] = pA0.x; As[kq*4+1][r] = pA0.y;                           \
            As[kq*4+2][r] = pA0.z; As[kq*4+3][r] = pA0.w;                           \
            int kq2 = kq + 2;                                                       \
            As[kq2*4+0][r] = pA1.x; As[kq2*4+1][r] = pA1.y;                         \
            As[kq2*4+2][r] = pA1.z; As[kq2*4+3][r] = pA1.w;                         \
            int k0 = tid >> 5, nq0 = tid & 31;                                      \
            *(float4*)(&Ws[k0][nq0*4]) = pW0;                                       \
            *(float4*)(&Ws[k0 + 8][nq0*4]) = pW1;                                   \
        }                                                                           \
        __syncthreads();                                                            \
        if (kc < 7) {                                                               \
            int kb = (kc + 1) * 16;                                                 \
            int r0 = tid & 127, kq0 = tid >> 7;                                     \
            int gr0 = br + r0;                                                      \
            pA0 = (gr0 < (Mval)) ? *(const float4*)((Aptr) + (size_t)gr0*Dd + kb + kq0*4) \
                                 : make_float4(0,0,0,0);                            \
            pA1 = (gr0 < (Mval)) ? *(const float4*)((Aptr) + (size_t)gr0*Dd + kb + (kq0+2)*4) \
                                 : make_float4(0,0,0,0);                            \
            int k0 = tid >> 5, nq0 = tid & 31;                                      \
            pW0 = *(const float4*)((Wptr) + (size_t)(kb + k0)*Dd + nq0*4);          \
            pW1 = *(const float4*)((Wptr) + (size_t)(kb + k0 + 8)*Dd + nq0*4);      \
        }                                                                           \
        _Pragma("unroll")                                                           \
        for (int k = 0; k < 16; k++) {                                              \
            float4 a0 = *(const float4*)(&As[k][ty*8]);                             \
            float4 a1 = *(const float4*)(&As[k][ty*8+4]);                           \
            const u64* w0 = (const u64*)(&Ws[k][tx*4]);                             \
            const u64* w1 = (const u64*)(&Ws[k][64 + tx*4]);                        \
            u64 bq0 = w0[0], bq1 = w0[1], bq2 = w1[0], bq3 = w1[1];                 \
            float av[8] = {a0.x,a0.y,a0.z,a0.w,a1.x,a1.y,a1.z,a1.w};                \
            _Pragma("unroll")                                                       \
            for (int i = 0; i < 8; i++) {                                           \
                u64 ad = pk2(av[i]);                                                \
                fma2(acc2[i][0], ad, bq0);                                          \
                fma2(acc2[i][1], ad, bq1);                                          \
                fma2(acc2[i][2], ad, bq2);                                          \
                fma2(acc2[i][3], ad, bq3);                                          \
            }                                                                       \
        }                                                                           \
    }

#define GEMM_UNPACK()                                                               \
    float acc[8][8];                                                                \
    _Pragma("unroll")                                                               \
    for (int i = 0; i < 8; i++) {                                                   \
        _Pragma("unroll")                                                           \
        for (int j2 = 0; j2 < 4; j2++)                                              \
            upk2(acc2[i][j2], acc[i][j2*2], acc[i][j2*2+1]);                        \
    }

// ---------------- GEMM: C[Mx128] = A[Mx128] @ W[128x128] (+ bias) ----------------
template <bool ALAR>
__global__ void __launch_bounds__(256, 2)
gemm_ff(const float* __restrict__ A, const float* __restrict__ Wbase,
        const float* __restrict__ bias, float* __restrict__ Cbase,
        const float* __restrict__ asb, const float* __restrict__ adb,
        float* __restrict__ al, float* __restrict__ ar, int M) {
    __shared__ float As[16][128];
    __shared__ float Ws[16][128];
    const int t = blockIdx.y;
    const float* W = Wbase + (size_t)t*Dd*Dd;
    float* C = Cbase + (size_t)t*M*Dd;
    const int br = blockIdx.x * 128;
    const int tid = threadIdx.x;
    const int tx = tid & 15, ty = tid >> 4;

    u64 acc2[8][4];
    #pragma unroll
    for (int i = 0; i < 8; i++)
        #pragma unroll
        for (int j = 0; j < 4; j++) acc2[i][j] = 0ull;

    GEMM_STAGE_AND_MAC(A, W, M)
    GEMM_UNPACK()

    float4 bb0 = make_float4(0,0,0,0), bb1 = make_float4(0,0,0,0);
    if (bias) {
        bb0 = *(const float4*)(bias + tx*4);
        bb1 = *(const float4*)(bias + 64 + tx*4);
    }
    float4 s0, s1, d0, d1;
    if (ALAR) {
        s0 = *(const float4*)(asb + t*Dd + tx*4);
        s1 = *(const float4*)(asb + t*Dd + 64 + tx*4);
        d0 = *(const float4*)(adb + t*Dd + tx*4);
        d1 = *(const float4*)(adb + t*Dd + 64 + tx*4);
    }
    #pragma unroll
    for (int i = 0; i < 8; i++) {
        int gr = br + ty*8 + i;
        float4 o0 = make_float4(acc[i][0]+bb0.x, acc[i][1]+bb0.y,
                                acc[i][2]+bb0.z, acc[i][3]+bb0.w);
        float4 o1 = make_float4(acc[i][4]+bb1.x, acc[i][5]+bb1.y,
                                acc[i][6]+bb1.z, acc[i][7]+bb1.w);
        if (gr < M) {
            *(float4*)(C + (size_t)gr*Dd + tx*4) = o0;
            *(float4*)(C + (size_t)gr*Dd + 64 + tx*4) = o1;
        }
        if (ALAR) {
            float pa0 = acc[i][0]*s0.x + acc[i][1]*s0.y + acc[i][2]*s0.z + acc[i][3]*s0.w;
            float pa1 = acc[i][4]*s1.x + acc[i][5]*s1.y + acc[i][6]*s1.z + acc[i][7]*s1.w;
            float pr0 = acc[i][0]*d0.x + acc[i][1]*d0.y + acc[i][2]*d0.z + acc[i][3]*d0.w;
            float pr1 = acc[i][4]*d1.x + acc[i][5]*d1.y + acc[i][6]*d1.z + acc[i][7]*d1.w;
            pa0 += __shfl_xor_sync(~0u, pa0, 1); pa0 += __shfl_xor_sync(~0u, pa0, 2);
            pa1 += __shfl_xor_sync(~0u, pa1, 1); pa1 += __shfl_xor_sync(~0u, pa1, 2);
            pr0 += __shfl_xor_sync(~0u, pr0, 1); pr0 += __shfl_xor_sync(~0u, pr0, 2);
            pr1 += __shfl_xor_sync(~0u, pr1, 1); pr1 += __shfl_xor_sync(~0u, pr1, 2);
            if (gr < M && (tx & 3) == 0) {
                int base = ((t*Nn) + gr)*Hh;
                int hh0 = tx >> 2, hh1 = 4 + (tx >> 2);
                al[base + hh0] = pa0;
                al[base + hh1] = pa1;
                ar[base + hh0] = pr0;
                ar[base + hh1] = pr1;
            }
        }
    }
}

// ---------------- fused k/q/v GEMM ----------------
__global__ void __launch_bounds__(256, 2)
gemm_kqv(const float* __restrict__ A,
         const float* __restrict__ Wk, const float* __restrict__ bk, float* __restrict__ Ck,
         const float* __restrict__ Wq, const float* __restrict__ bq, float* __restrict__ Cq,
         const float* __restrict__ Wv, const float* __restrict__ bv, float* __restrict__ Cv) {
    __shared__ float As[16][128];
    __shared__ float Ws[16][128];
    const int t = blockIdx.y;
    const float* W = (t == 0) ? Wk : (t == 1) ? Wq : Wv;
    const float* bias = (t == 0) ? bk : (t == 1) ? bq : bv;
    float* C = (t == 0) ? Ck : (t == 1) ? Cq : Cv;
    const int br = blockIdx.x * 128;
    const int tid = threadIdx.x;
    const int tx = tid & 15, ty = tid >> 4;

    u64 acc2[8][4];
    #pragma unroll
    for (int i = 0; i < 8; i++)
        #pragma unroll
        for (int j = 0; j < 4; j++) acc2[i][j] = 0ull;

    GEMM_STAGE_AND_MAC(A, W, Nn)
    GEMM_UNPACK()

    float4 bb0 = *(const float4*)(bias + tx*4);
    float4 bb1 = *(const float4*)(bias + 64 + tx*4);
    #pragma unroll
    for (int i = 0; i < 8; i++) {
        int gr = br + ty*8 + i;
        if (gr < Nn) {
            *(float4*)(C + (size_t)gr*Dd + tx*4) =
                make_float4(acc[i][0]+bb0.x, acc[i][1]+bb0.y, acc[i][2]+bb0.z, acc[i][3]+bb0.w);
            *(float4*)(C + (size_t)gr*Dd + 64 + tx*4) =
                make_float4(acc[i][4]+bb1.x, acc[i][5]+bb1.y, acc[i][6]+bb1.z, acc[i][7]+bb1.w);
        }
    }
}

// ---------------- Final GEMM + HGT post fused ----------------------------------
__global__ void __launch_bounds__(256, 2)
gemm_wo_post(const float* __restrict__ A, const float* __restrict__ W,
             const float* __restrict__ bias, const float* __restrict__ h,
             const float* __restrict__ g, const float* __restrict__ skip,
             float* __restrict__ out) {
    __shared__ float As[16][128];
    __shared__ float Ws[16][128];
    const int br = blockIdx.x * 128;
    const int tid = threadIdx.x;
    const int tx = tid & 15, ty = tid >> 4;

    u64 acc2[8][4];
    #pragma unroll
    for (int i = 0; i < 8; i++)
        #pragma unroll
        for (int j = 0; j < 4; j++) acc2[i][j] = 0ull;

    GEMM_STAGE_AND_MAC(A, W, Nn)
    GEMM_UNPACK()

    float beta = 1.f / (1.f + expf(-skip[0]));
    float omb = 1.f - beta;
    float4 bb0 = *(const float4*)(bias + tx*4);
    float4 bb1 = *(const float4*)(bias + 64 + tx*4);
    float4 g0 = *(const float4*)(g + tx*4);
    float4 g1 = *(const float4*)(g + 64 + tx*4);

    #pragma unroll
    for (int i = 0; i < 8; i++) {
        int gr = br + ty*8 + i;
        if (gr >= Nn) continue;
        float4 h0 = *(const float4*)(h + (size_t)gr*Dd + tx*4);
        float4 h1 = *(const float4*)(h + (size_t)gr*Dd + 64 + tx*4);
        float u[8];
        u[0] = beta*(acc[i][0]+bb0.x) + omb*h0.x;
        u[1] = beta*(acc[i][1]+bb0.y) + omb*h0.y;
        u[2] = beta*(acc[i][2]+bb0.z) + omb*h0.z;
        u[3] = beta*(acc[i][3]+bb0.w) + omb*h0.w;
        u[4] = beta*(acc[i][4]+bb1.x) + omb*h1.x;
        u[5] = beta*(acc[i][5]+bb1.y) + omb*h1.y;
        u[6] = beta*(acc[i][6]+bb1.z) + omb*h1.z;
        u[7] = beta*(acc[i][7]+bb1.w) + omb*h1.w;
        float ss = 0.f;
        #pragma unroll
        for (int j = 0; j < 8; j++) ss += u[j]*u[j];
        ss += __shfl_xor_sync(~0u, ss, 1);
        ss += __shfl_xor_sync(~0u, ss, 2);
        ss += __shfl_xor_sync(~0u, ss, 4);
        ss += __shfl_xor_sync(~0u, ss, 8);
        float inv = rsqrtf(ss * (1.0f/Dd) + EPSF);
        float4 r0, r1;
        r0.x = geluf(h0.x + g0.x*u[0]*inv);
        r0.y = geluf(h0.y + g0.y*u[1]*inv);
        r0.z = geluf(h0.z + g0.z*u[2]*inv);
        r0.w = geluf(h0.w + g0.w*u[3]*inv);
        r1.x = geluf(h1.x + g1.x*u[4]*inv);
        r1.y = geluf(h1.y + g1.y*u[5]*inv);
        r1.z = geluf(h1.z + g1.z*u[6]*inv);
        r1.w = geluf(h1.w + g1.w*u[7]*inv);
        *(float4*)(out + (size_t)gr*Dd + tx*4) = r0;
        *(float4*)(out + (size_t)gr*Dd + 64 + tx*4) = r1;
    }
}

// ---------------- GAT gather (round-9 version, unchanged) ----------------
__global__ void gat_gather_b(const int* __restrict__ csr, const int* __restrict__ off,
                             const int* __restrict__ deg, const float* __restrict__ al,
                             const float* __restrict__ ar, const float* __restrict__ xw,
                             const float* __restrict__ b, const float* __restrict__ g,
                             float* __restrict__ h) {
    int n = blockIdx.x;
    int tid = threadIdx.x;
    int t = tid >> 5, lane = tid & 31;
    int hh = lane >> 2;
    __shared__ float smf[4][128];
    __shared__ float sw[4];

    {
        int i = t*Nn + n;
        float arn = ar[(size_t)i*Hh + hh];
        float v = al[(size_t)i*Hh + hh] + arn;    // self loop
        v = v > 0.f ? v : NEG_SLOPE*v;
        float p = expf(v);
        float s = p;
        float4 x = *(const float4*)(xw + (size_t)i*Dd + lane*4);
        float4 f = make_float4(x.x*p, x.y*p, x.z*p, x.w*p);

        const float* alt = al + (size_t)t*Nn*Hh;
        const float* xwt = xw + (size_t)t*Nn*Dd;
        int st = off[i], dg = deg[i];
        for (int j0 = 0; j0 < dg; j0 += 32) {
            int myS = (j0 + lane < dg) ? csr[st + j0 + lane] : 0;
            int cnt = min(32, dg - j0);
            for (int j = 0; j < cnt; j += 4) {
                int s0 = __shfl_sync(~0u, myS, j);
                int s1 = __shfl_sync(~0u, myS, (j+1) & 31);
                int s2 = __shfl_sync(~0u, myS, (j+2) & 31);
                int s3 = __shfl_sync(~0u, myS, (j+3) & 31);
                float a0 = alt[(size_t)s0*Hh + hh];
                float a1 = alt[(size_t)s1*Hh + hh];
                float a2 = alt[(size_t)s2*Hh + hh];
                float a3 = alt[(size_t)s3*Hh + hh];
                float4 x0 = *(const float4*)(xwt + (size_t)s0*Dd + lane*4);
                float4 x1 = *(const float4*)(xwt + (size_t)s1*Dd + lane*4);
                float4 x2 = *(const float4*)(xwt + (size_t)s2*Dd + lane*4);
                float4 x3 = *(const float4*)(xwt + (size_t)s3*Dd + lane*4);
                float v0 = a0 + arn; v0 = v0 > 0.f ? v0 : NEG_SLOPE*v0;
                float v1 = a1 + arn; v1 = v1 > 0.f ? v1 : NEG_SLOPE*v1;
                float v2 = a2 + arn; v2 = v2 > 0.f ? v2 : NEG_SLOPE*v2;
                float v3 = a3 + arn; v3 = v3 > 0.f ? v3 : NEG_SLOPE*v3;
                float p0 = expf(v0);
                float p1 = (j+1 < cnt) ? expf(v1) : 0.f;
                float p2 = (j+2 < cnt) ? expf(v2) : 0.f;
                float p3 = (j+3 < cnt) ? expf(v3) : 0.f;
                s += p0 + p1 + p2 + p3;
                f.x += x0.x*p0 + x1.x*p1 + x2.x*p2 + x3.x*p3;
                f.y += x0.y*p0 + x1.y*p1 + x2.y*p2 + x3.y*p3;
                f.z += x0.z*p0 + x1.z*p1 + x2.z*p2 + x3.z*p3;
                f.w += x0.w*p0 + x1.w*p1 + x2.w*p2 + x3.w*p3;
            }
        }
        float inv = 1.f / s;
        *(float4*)(&smf[t][lane*4]) = make_float4(f.x*inv, f.y*inv, f.z*inv, f.w*inv);
    }
    __syncthreads();

    int d = tid;
    float a = smf[0][d] + smf[1][d] + smf[2][d] + smf[3][d]
            + b[d] + b[Dd + d] + b[2*Dd + d] + b[3*Dd + d];
    float ss = a*a;
    #pragma unroll
    for (int o = 16; o > 0; o >>= 1) ss += __shfl_xor_sync(0xffffffffu, ss, o);
    if (lane == 0) sw[t] = ss;
    __syncthreads();
    float tot = sw[0] + sw[1] + sw[2] + sw[3];
    float inv2 = rsqrtf(tot * (1.0f/Dd) + EPSF);
    int i = n*Dd + d;
    h[i] = geluf(h[i] + g[d] * a * inv2);
}

// ---------------- HGT gather (round-9 version, unchanged) ----------------
__global__ void hgt_gather_b(const int* __restrict__ csr, const int* __restrict__ off,
                             const int* __restrict__ deg, const float* __restrict__ k,
                             const float* __restrict__ q, const float* __restrict__ v,
                             const float* __restrict__ arel, const float* __restrict__ mrel,
                             const float* __restrict__ prel, float* __restrict__ out) {
    int n = blockIdx.x;
    int tid = threadIdx.x;
    int t = tid >> 5, lane = tid & 31;
    int hh = lane >> 2, qd = lane & 3;
    int qbase = lane & ~3;
    __shared__ float smacc[4][128];
    __shared__ float sms[4][8];

    {
        float4 qv = *(const float4*)(q + (size_t)n*Dd + lane*4);
        const float* A = arel + (size_t)((t*Hh + hh)*16)*16;
        float4 qA = make_float4(0,0,0,0);
        #pragma unroll
        for (int fq = 0; fq < 4; fq++) {
            float4 qb = shfl4(qv, qbase | fq);
            #pragma unroll
            for (int i = 0; i < 4; i++) {
                float4 a4 = *(const float4*)(A + (qd*4 + i)*16 + fq*4);
                float val = dot4(a4, qb);
                if (i == 0) qA.x += val;
                else if (i == 1) qA.y += val;
                else if (i == 2) qA.z += val;
                else qA.w += val;
            }
        }
        float pr = prel[t*Hh + hh] * 0.25f;

        float4 aggv = make_float4(0,0,0,0);
        float s = 0.f;
        int i0 = t*Nn + n, st = off[i0], dg = deg[i0];
        for (int j0 = 0; j0 < dg; j0 += 32) {
            int myS = (j0 + lane < dg) ? csr[st + j0 + lane] : 0;
            int cnt = min(32, dg - j0);
            for (int j = 0; j < cnt; j += 4) {
                int s0 = __shfl_sync(~0u, myS, j);
                int s1 = __shfl_sync(~0u, myS, (j+1) & 31);
                int s2 = __shfl_sync(~0u, myS, (j+2) & 31);
                int s3 = __shfl_sync(~0u, myS, (j+3) & 31);
                float4 k0 = *(const float4*)(k + (size_t)s0*Dd + lane*4);
                float4 k1 = *(const float4*)(k + (size_t)s1*Dd + lane*4);
                float4 k2 = *(const float4*)(k + (size_t)s2*Dd + lane*4);
                float4 k3 = *(const float4*)(k + (size_t)s3*Dd + lane*4);
                float4 v0 = *(const float4*)(v + (size_t)s0*Dd + lane*4);
                float4 v1 = *(const float4*)(v + (size_t)s1*Dd + lane*4);
                float4 v2 = *(const float4*)(v + (size_t)s2*Dd + lane*4);
                float4 v3 = *(const float4*)(v + (size_t)s3*Dd + lane*4);
                float pt0 = dot4(k0, qA);
                float pt1 = dot4(k1, qA);
                float pt2 = dot4(k2, qA);
                float pt3 = dot4(k3, qA);
                pt0 += __shfl_xor_sync(~0u, pt0, 1); pt0 += __shfl_xor_sync(~0u, pt0, 2);
                pt1 += __shfl_xor_sync(~0u, pt1, 1); pt1 += __shfl_xor_sync(~0u, pt1, 2);
                pt2 += __shfl_xor_sync(~0u, pt2, 1); pt2 += __shfl_xor_sync(~0u, pt2, 2);
                pt3 += __shfl_xor_sync(~0u, pt3, 1); pt3 += __shfl_xor_sync(~0u, pt3, 2);
                float p0 = expf(pt0 * pr);
                float p1 = (j+1 < cnt) ? expf(pt1 * pr) : 0.f;
                float p2 = (j+2 < cnt) ? expf(pt2 * pr) : 0.f;
                float p3 = (j+3 < cnt) ? expf(pt3 * pr) : 0.f;
                s += p0 + p1 + p2 + p3;
                aggv.x += v0.x*p0 + v1.x*p1 + v2.x*p2 + v3.x*p3;
                aggv.y += v0.y*p0 + v1.y*p1 + v2.y*p2 + v3.y*p3;
                aggv.z += v0.z*p0 + v1.z*p1 + v2.z*p2 + v3.z*p3;
                aggv.w += v0.w*p0 + v1.w*p1 + v2.w*p2 + v3.w*p3;
            }
        }
        const float* M = mrel + (size_t)((t*Hh + hh)*16)*16;
        float4 acc = make_float4(0,0,0,0);
        #pragma unroll
        for (int dq = 0; dq < 4; dq++) {
            float4 ab = shfl4(aggv, qbase | dq);
            float av[4] = {ab.x, ab.y, ab.z, ab.w};
            #pragma unroll
            for (int j = 0; j < 4; j++) {
                float4 m4 = *(const float4*)(M + (dq*4 + j)*16 + qd*4);
                float aj = av[j];
                acc.x += aj*m4.x; acc.y += aj*m4.y; acc.z += aj*m4.z; acc.w += aj*m4.w;
            }
        }
        *(float4*)(&smacc[t][lane*4]) = acc;
        if (qd == 0) sms[t][hh] = s;
    }
    __syncthreads();

    int d = tid;
    int dh = d >> 4;
    float a = smacc[0][d] + smacc[1][d] + smacc[2][d] + smacc[3][d];
    float stot = sms[0][dh] + sms[1][dh] + sms[2][dh] + sms[3][dh];
    float inv = 1.f / (stot > 0.f ? stot : 1.f);
    out[(size_t)n*Dd + d] = geluf(a * inv);
}

// ---------------- host launch ----------------
extern "C" void kernel_launch(void* const* d_in, const int* in_sizes, int n_in,
                              void* d_out, int out_size) {
    const float* zL  = (const float*)d_in[0];
    const float* zH  = (const float*)d_in[1];
    const float* xe  = (const float*)d_in[2];
    const float* W1  = (const float*)d_in[3];
    const float* as1 = (const float*)d_in[4];
    const float* ad1 = (const float*)d_in[5];
    const float* b1  = (const float*)d_in[6];
    const float* W2  = (const float*)d_in[7];
    const float* as2 = (const float*)d_in[8];
    const float* ad2 = (const float*)d_in[9];
    const float* b2  = (const float*)d_in[10];
    const float* Wk  = (const float*)d_in[11];
    const float* bk  = (const float*)d_in[12];
    const float* Wq  = (const float*)d_in[13];
    const float* bq  = (const float*)d_in[14];
    const float* Wv  = (const float*)d_in[15];
    const float* bv  = (const float*)d_in[16];
    const float* arel= (const float*)d_in[17];
    const float* mrel= (const float*)d_in[18];
    const float* prel= (const float*)d_in[19];
    const float* Wo  = (const float*)d_in[20];
    const float* bo  = (const float*)d_in[21];
    const float* skip= (const float*)d_in[22];
    const float* g1  = (const float*)d_in[23];
    const float* g2  = (const float*)d_in[24];
    const float* g3  = (const float*)d_in[25];
    const int* ei[4] = {(const int*)d_in[26], (const int*)d_in[27],
                        (const int*)d_in[28], (const int*)d_in[29]};

    float *h_, *k_, *q_, *v_, *tmp_, *al_, *ar_, *xw_;
    int *deg_, *off_, *cur_, *csr_, *bsum_;
    cudaGetSymbolAddress((void**)&h_,   g_h);
    cudaGetSymbolAddress((void**)&k_,   g_k);
    cudaGetSymbolAddress((void**)&q_,   g_q);
    cudaGetSymbolAddress((void**)&v_,   g_v);
    cudaGetSymbolAddress((void**)&tmp_, g_tmp);
    cudaGetSymbolAddress((void**)&al_,  g_al);
    cudaGetSymbolAddress((void**)&ar_,  g_ar);
    cudaGetSymbolAddress((void**)&xw_,  g_xw);
    cudaGetSymbolAddress((void**)&deg_, g_deg);
    cudaGetSymbolAddress((void**)&off_, g_off);
    cudaGetSymbolAddress((void**)&cur_, g_cur);
    cudaGetSymbolAddress((void**)&csr_, g_csr);
    cudaGetSymbolAddress((void**)&bsum_,g_bsum);

    const int nd = Nn*Dd;
    const int TPB = 256;
    const int gemm_grid = (Nn + 127) / 128;

    // Launch order: gemm_ff<true> is launch #4 (ncu captures #4).
    zeroint<<<(TN + TPB-1)/TPB, TPB>>>(deg_, TN);                                   // 1
    deg_k<<<(E4 + TPB-1)/TPB, TPB>>>(ei[0], ei[1], ei[2], ei[3], deg_);             // 2
    add3k<<<(nd/4 + TPB-1)/TPB, TPB>>>((const float4*)zL, (const float4*)zH,
                                       (const float4*)xe, (float4*)h_, nd/4);       // 3
    gemm_ff<true><<<dim3(gemm_grid, Tt), TPB>>>(h_, W1, nullptr, xw_,
                                                as1, ad1, al_, ar_, Nn);            // 4 (profiled)
    scan_pre<<<SCAN_NB, 1024>>>(deg_, bsum_);                                       // 5
    scan_mid<<<1, 256>>>(bsum_);                                                    // 6
    scan_post<<<SCAN_NB, 1024>>>(deg_, bsum_, off_, cur_);                          // 7
    fill_k<<<(E4 + TPB-1)/TPB, TPB>>>(ei[0], ei[1], ei[2], ei[3], cur_, csr_);      // 8

    gat_gather_b<<<Nn, 128>>>(csr_, off_, deg_, al_, ar_, xw_, b1, g1, h_);         // 9

    // GAT layer 2
    gemm_ff<true><<<dim3(gemm_grid, Tt), TPB>>>(h_, W2, nullptr, xw_,
                                                as2, ad2, al_, ar_, Nn);            // 10
    gat_gather_b<<<Nn, 128>>>(csr_, off_, deg_, al_, ar_, xw_, b2, g2, h_);         // 11

    // HGT
    gemm_kqv<<<dim3(gemm_grid, 3), TPB>>>(h_, Wk, bk, k_, Wq, bq, q_, Wv, bv, v_);  // 12
    hgt_gather_b<<<Nn, 128>>>(csr_, off_, deg_, k_, q_, v_, arel, mrel, prel, tmp_);// 13
    gemm_wo_post<<<gemm_grid, TPB>>>(tmp_, Wo, bo, h_, g3, skip, (float*)d_out);    // 14
}